// round 6
// baseline (speedup 1.0000x reference)
#include <cuda_runtime.h>
#include <math.h>

// Problem constants
#define B_ 512
#define T_ 256
#define C_ 384
#define H_ 64
#define M_TOTAL (B_ * T_)   // 131072

typedef unsigned long long ull;

// ---------------------------------------------------------------------------
// Scratch (no cudaMalloc allowed): K,Q,V projections, [B,T,H] each, fp32.
// ---------------------------------------------------------------------------
__device__ __align__(16) float g_k[(size_t)B_ * T_ * H_];
__device__ __align__(16) float g_q[(size_t)B_ * T_ * H_];
__device__ __align__(16) float g_v[(size_t)B_ * T_ * H_];

// ---------------------------------------------------------------------------
// Packed f32x2 helpers (Blackwell sm_100+: fma.rn.f32x2 / mul.rn.f32x2)
// ---------------------------------------------------------------------------
__device__ __forceinline__ ull pack2(float lo, float hi) {
    ull r;
    asm("mov.b64 %0, {%1, %2};" : "=l"(r)
        : "r"(__float_as_uint(lo)), "r"(__float_as_uint(hi)));
    return r;
}
__device__ __forceinline__ void unpack2(ull v, float& lo, float& hi) {
    unsigned int a, b;
    asm("mov.b64 {%0, %1}, %2;" : "=r"(a), "=r"(b) : "l"(v));
    lo = __uint_as_float(a);
    hi = __uint_as_float(b);
}
__device__ __forceinline__ ull fma2(ull a, ull b, ull c) {
    ull d;
    asm("fma.rn.f32x2 %0, %1, %2, %3;" : "=l"(d) : "l"(a), "l"(b), "l"(c));
    return d;
}
__device__ __forceinline__ ull mul2(ull a, ull b) {
    ull d;
    asm("mul.rn.f32x2 %0, %1, %2;" : "=l"(d) : "l"(a), "l"(b));
    return d;
}
__device__ __forceinline__ ull add2(ull a, ull b) {
    ull d;
    asm("add.rn.f32x2 %0, %1, %2;" : "=l"(d) : "l"(a), "l"(b));
    return d;
}

// cp.async helpers (LDGSTS, 16B)
__device__ __forceinline__ unsigned int smem_u32(const void* p) {
    unsigned int a;
    asm("{ .reg .u64 t; cvta.to.shared.u64 t, %1; cvt.u32.u64 %0, t; }"
        : "=r"(a) : "l"(p));
    return a;
}
__device__ __forceinline__ void cp16(unsigned int dst, const void* src) {
    asm volatile("cp.async.cg.shared.global [%0], [%1], 16;"
                 :: "r"(dst), "l"(src) : "memory");
}
__device__ __forceinline__ void cp_commit() {
    asm volatile("cp.async.commit_group;" ::: "memory");
}
__device__ __forceinline__ void cp_wait0() {
    asm volatile("cp.async.wait_group 0;" ::: "memory");
}

// ---------------------------------------------------------------------------
// Projection GEMM: out = X @ W, X:[131072,384], W:[384,64].
// Tile: 128(M) x 64(N), K-chunk 32. 256 threads, thread tile 4(M) x 8(N)
// computed as 4 x (4 f32x2 pairs). blockIdx.y selects {Wk, Wq, Wv}.
// Double-buffered smem (register-staged prefetch) -> 1 barrier per K-chunk,
// GMEM latency hidden behind the 512-FFMA2 compute phase. occ=2.
// ---------------------------------------------------------------------------
__global__ __launch_bounds__(256, 2)
void proj_kernel(const float* __restrict__ X,
                 const float* __restrict__ Wk,
                 const float* __restrict__ Wq,
                 const float* __restrict__ Wv) {
    __shared__ __align__(16) float As[2][128][36]; // stride 36 keeps 16B align
    __shared__ __align__(16) float Bs[2][32][64];

    const int tid = threadIdx.x;
    const int wsel = blockIdx.y;
    const float* __restrict__ W = (wsel == 0) ? Wk : (wsel == 1) ? Wq : Wv;
    float* __restrict__ dst = (wsel == 0) ? g_k : (wsel == 1) ? g_q : g_v;

    const size_t m0 = (size_t)blockIdx.x * 128;

    const int tx = tid & 7;    // 0..7   -> n0 = tx*8
    const int ty = tid >> 3;   // 0..31  -> rows ty*4 .. ty*4+3
    const int n0 = tx * 8;
    const int r0 = ty * 4;

    // Per-thread load coordinates (independent of k0)
    int aRow[4], aC4[4];
#pragma unroll
    for (int i = 0; i < 4; i++) {
        int idx = tid + i * 256;
        aRow[i] = idx >> 3;      // 8 float4 per row
        aC4[i]  = idx & 7;
    }
    int bRow[2], bC4[2];
#pragma unroll
    for (int i = 0; i < 2; i++) {
        int idx = tid + i * 256;
        bRow[i] = idx >> 4;      // 16 float4 per row
        bC4[i]  = idx & 15;
    }

    float4 aReg[4], bReg[2];

    // ---- prefetch k0 = 0 ----
#pragma unroll
    for (int i = 0; i < 4; i++)
        aReg[i] = *(const float4*)&X[(m0 + aRow[i]) * C_ + aC4[i] * 4];
#pragma unroll
    for (int i = 0; i < 2; i++)
        bReg[i] = *(const float4*)&W[(size_t)bRow[i] * H_ + bC4[i] * 4];
#pragma unroll
    for (int i = 0; i < 4; i++)
        *(float4*)&As[0][aRow[i]][aC4[i] * 4] = aReg[i];
#pragma unroll
    for (int i = 0; i < 2; i++)
        *(float4*)&Bs[0][bRow[i]][bC4[i] * 4] = bReg[i];
    __syncthreads();

    ull acc[4][4];
#pragma unroll
    for (int i = 0; i < 4; i++)
#pragma unroll
        for (int j = 0; j < 4; j++) acc[i][j] = 0ULL;

    int p = 0;
    for (int k0 = 0; k0 < C_; k0 += 32) {
        const bool more = (k0 + 32 < C_);
        // ---- issue next tile's global loads (latency overlapped w/ compute)
        if (more) {
            const int kn = k0 + 32;
#pragma unroll
            for (int i = 0; i < 4; i++)
                aReg[i] = *(const float4*)&X[(m0 + aRow[i]) * C_ + kn + aC4[i] * 4];
#pragma unroll
            for (int i = 0; i < 2; i++)
                bReg[i] = *(const float4*)&W[(size_t)(kn + bRow[i]) * H_ + bC4[i] * 4];
        }

        // ---- compute on buffer p ----
#pragma unroll 8
        for (int kk = 0; kk < 32; kk++) {
            const ulonglong2 bv0 = *(const ulonglong2*)&Bs[p][kk][n0];
            const ulonglong2 bv1 = *(const ulonglong2*)&Bs[p][kk][n0 + 4];
            const ull bp0 = bv0.x, bp1 = bv0.y, bp2 = bv1.x, bp3 = bv1.y;
#pragma unroll
            for (int i = 0; i < 4; i++) {
                const float a = As[p][r0 + i][kk];
                const ull a2 = pack2(a, a);
                acc[i][0] = fma2(a2, bp0, acc[i][0]);
                acc[i][1] = fma2(a2, bp1, acc[i][1]);
                acc[i][2] = fma2(a2, bp2, acc[i][2]);
                acc[i][3] = fma2(a2, bp3, acc[i][3]);
            }
        }

        // ---- store next tile into the other buffer, single barrier ----
        if (more) {
            const int np = p ^ 1;
#pragma unroll
            for (int i = 0; i < 4; i++)
                *(float4*)&As[np][aRow[i]][aC4[i] * 4] = aReg[i];
#pragma unroll
            for (int i = 0; i < 2; i++)
                *(float4*)&Bs[np][bRow[i]][bC4[i] * 4] = bReg[i];
            __syncthreads();
            p = np;
        }
    }

    // ---- epilogue ----
#pragma unroll
    for (int i = 0; i < 4; i++) {
        float* outr = dst + (m0 + r0 + i) * H_ + n0;
#pragma unroll
        for (int j = 0; j < 4; j++) {
            float lo, hi;
            unpack2(acc[i][j], lo, hi);
            *(float2*)&outr[2 * j] = make_float2(lo, hi);
        }
    }
}

// ---------------------------------------------------------------------------
// Attention: one block per batch. SMSP-balanced warp->query-range map:
//   warp w (SMSP = w%4) handles queries qbase(w)..qbase(w)+31 where
//   qbase = (w<4 ? 7-w : w-4)*32. Warp pairs on one SMSP then sum to a
//   constant 286 key-units of causal work (vs 382 worst-case for the
//   identity map) -> ~25% shorter critical path.
// Online (flash-style) softmax. K/V staged in DOUBLE-BUFFERED dynamic smem
// (64 KB) via cp.async; one barrier per chunk. Whole warps skip fully-masked
// chunks; threads skip fully-masked 8-blocks; rescale skipped when the
// running max is unchanged.
// smem layout (floats): buf p at p*8192; K tile at +0, V tile at +4096.
// ---------------------------------------------------------------------------
__global__ __launch_bounds__(256, 1)
void attn_kernel(float* __restrict__ out) {
    extern __shared__ __align__(16) float sm[];

    const int b = blockIdx.x;
    const int t = threadIdx.x;
    const int w = t >> 5;
    const int lane = t & 31;
    // SMSP-balanced query assignment
    const int q = ((w < 4) ? (7 - w) : (w - 4)) * 32 + lane;

    const unsigned int sbase = smem_u32(sm);

    // Per-thread cp.async coordinates: 1024 float4 per tile, 4 per thread.
    int ldRow[4], ldC4[4];
#pragma unroll
    for (int i = 0; i < 4; i++) {
        int idx = t + i * 256;
        ldRow[i] = idx >> 4;     // 16 float4 per 64-float row
        ldC4[i]  = idx & 15;
    }

    // Load own query row (64 floats = 32 packed pairs)
    ull q2[32];
    {
        const ulonglong2* qp =
            (const ulonglong2*)(g_q + ((size_t)b * T_ + q) * H_);
#pragma unroll
        for (int h4 = 0; h4 < 16; h4++) {
            ulonglong2 v = qp[h4];
            q2[2 * h4]     = v.x;
            q2[2 * h4 + 1] = v.y;
        }
    }

    ull a2[32];
#pragma unroll
    for (int h2 = 0; h2 < 32; h2++) a2[h2] = 0ULL;
    float m = -INFINITY;
    float l = 0.0f;

    // ---- issue chunk 0 into buffer 0 ----
    {
        const size_t base = (size_t)b * T_ * H_;
#pragma unroll
        for (int i = 0; i < 4; i++) {
            const unsigned int off = (unsigned)(ldRow[i] * 256 + ldC4[i] * 16);
            cp16(sbase + off,          &g_k[base + (size_t)ldRow[i] * H_ + ldC4[i] * 4]);
            cp16(sbase + 16384 + off,  &g_v[base + (size_t)ldRow[i] * H_ + ldC4[i] * 4]);
        }
        cp_commit();
    }

    int p = 0;
    for (int c = 0; c < 4; c++) {
        cp_wait0();
        __syncthreads();   // chunk c resident AND all threads done with buf p^1

        // ---- issue chunk c+1 into the other buffer (overlaps compute) ----
        if (c < 3) {
            const size_t base = ((size_t)b * T_ + (c + 1) * 64) * H_;
            const unsigned int bb = sbase + (unsigned)((p ^ 1) * 32768);
#pragma unroll
            for (int i = 0; i < 4; i++) {
                const unsigned int off = (unsigned)(ldRow[i] * 256 + ldC4[i] * 16);
                cp16(bb + off,         &g_k[base + (size_t)ldRow[i] * H_ + ldC4[i] * 4]);
                cp16(bb + 16384 + off, &g_v[base + (size_t)ldRow[i] * H_ + ldC4[i] * 4]);
            }
            cp_commit();
        }

        const int smax = c * 64;
        if ((q | 31) >= smax) {              // warp has >=1 unmasked query
            const float* Ks = sm + p * 8192;
            const float* Vs = sm + p * 8192 + 4096;

            for (int j0 = 0; j0 < 64; j0 += 8) {
                if (smax + j0 > q) break;    // rest of chunk fully masked

                // ---- scores for 8 keys ----
                float sc[8];
#pragma unroll
                for (int jj = 0; jj < 8; jj++) {
                    const ulonglong2* kp =
                        (const ulonglong2*)&Ks[(j0 + jj) * 64];
                    ull d2a = 0ULL, d2b = 0ULL;
#pragma unroll
                    for (int h4 = 0; h4 < 16; h4++) {
                        ulonglong2 kv = kp[h4];
                        d2a = fma2(q2[2 * h4],     kv.x, d2a);
                        d2b = fma2(q2[2 * h4 + 1], kv.y, d2b);
                    }
                    float lo, hi;
                    unpack2(add2(d2a, d2b), lo, hi);
                    float s = (lo + hi) * 0.125f;   // HEAD_SIZE^-0.5 = 1/8
                    if (smax + j0 + jj > q) s = -INFINITY;
                    sc[jj] = s;
                }

                // ---- online softmax update ----
                float mx = sc[0];
#pragma unroll
                for (int jj = 1; jj < 8; jj++) mx = fmaxf(mx, sc[jj]);
                const float m_new = fmaxf(m, mx);
                float wgt[8];
                float ls = 0.0f;
#pragma unroll
                for (int jj = 0; jj < 8; jj++) {
                    wgt[jj] = __expf(sc[jj] - m_new);
                    ls += wgt[jj];
                }
                if (m_new > m) {             // rescale only when max moved
                    const float scale = __expf(m - m_new);
                    l = l * scale + ls;
                    const ull s2 = pack2(scale, scale);
#pragma unroll
                    for (int h2 = 0; h2 < 32; h2++) a2[h2] = mul2(a2[h2], s2);
                    m = m_new;
                } else {
                    l += ls;
                }

                // ---- accumulate V ----
#pragma unroll
                for (int jj = 0; jj < 8; jj++) {
                    const ull w2 = pack2(wgt[jj], wgt[jj]);
                    const ulonglong2* vp =
                        (const ulonglong2*)&Vs[(j0 + jj) * 64];
#pragma unroll
                    for (int h4 = 0; h4 < 16; h4++) {
                        ulonglong2 vv = vp[h4];
                        a2[2 * h4]     = fma2(w2, vv.x, a2[2 * h4]);
                        a2[2 * h4 + 1] = fma2(w2, vv.y, a2[2 * h4 + 1]);
                    }
                }
            }
        }
        p ^= 1;
    }

    // ---- normalize and write out[b][q][:] ----
    const float inv = 1.0f / l;
    float* outr = out + ((size_t)b * T_ + q) * H_;
#pragma unroll
    for (int h2 = 0; h2 < 32; h2++) {
        float lo, hi;
        unpack2(a2[h2], lo, hi);
        *(float2*)&outr[2 * h2] = make_float2(lo * inv, hi * inv);
    }
}

// ---------------------------------------------------------------------------
// Launch: inputs per metadata order: x, Wk, Wq, Wv (all float32).
// Output: [B, T, H] float32.
// NOTE: no static guards anywhere (harness rule). cudaFuncSetAttribute is a
// host-side, non-stream, non-allocating API: graph-capture legal, idempotent,
// called unconditionally on every invocation.
// ---------------------------------------------------------------------------
extern "C" void kernel_launch(void* const* d_in, const int* in_sizes, int n_in,
                              void* d_out, int out_size) {
    const float* x  = (const float*)d_in[0];
    const float* Wk = (const float*)d_in[1];
    const float* Wq = (const float*)d_in[2];
    const float* Wv = (const float*)d_in[3];
    float* out = (float*)d_out;

    cudaFuncSetAttribute(attn_kernel,
                         cudaFuncAttributeMaxDynamicSharedMemorySize,
                         64 * 1024);

    dim3 pgrid(M_TOTAL / 128, 3);
    proj_kernel<<<pgrid, 256>>>(x, Wk, Wq, Wv);
    attn_kernel<<<B_, 256, 64 * 1024>>>(out);
}

// round 7
// speedup vs baseline: 1.0350x; 1.0350x over previous
#include <cuda_runtime.h>
#include <math.h>

// Problem constants
#define B_ 512
#define T_ 256
#define C_ 384
#define H_ 64
#define M_TOTAL (B_ * T_)   // 131072

typedef unsigned long long ull;

// ---------------------------------------------------------------------------
// Scratch (no cudaMalloc allowed): K,Q,V projections, [B,T,H] each, fp32.
// ---------------------------------------------------------------------------
__device__ __align__(16) float g_k[(size_t)B_ * T_ * H_];
__device__ __align__(16) float g_q[(size_t)B_ * T_ * H_];
__device__ __align__(16) float g_v[(size_t)B_ * T_ * H_];

// ---------------------------------------------------------------------------
// Packed f32x2 helpers (Blackwell sm_100+: fma.rn.f32x2 / mul.rn.f32x2)
// ---------------------------------------------------------------------------
__device__ __forceinline__ ull pack2(float lo, float hi) {
    ull r;
    asm("mov.b64 %0, {%1, %2};" : "=l"(r)
        : "r"(__float_as_uint(lo)), "r"(__float_as_uint(hi)));
    return r;
}
__device__ __forceinline__ void unpack2(ull v, float& lo, float& hi) {
    unsigned int a, b;
    asm("mov.b64 {%0, %1}, %2;" : "=r"(a), "=r"(b) : "l"(v));
    lo = __uint_as_float(a);
    hi = __uint_as_float(b);
}
__device__ __forceinline__ ull fma2(ull a, ull b, ull c) {
    ull d;
    asm("fma.rn.f32x2 %0, %1, %2, %3;" : "=l"(d) : "l"(a), "l"(b), "l"(c));
    return d;
}
__device__ __forceinline__ ull mul2(ull a, ull b) {
    ull d;
    asm("mul.rn.f32x2 %0, %1, %2;" : "=l"(d) : "l"(a), "l"(b));
    return d;
}
__device__ __forceinline__ ull add2(ull a, ull b) {
    ull d;
    asm("add.rn.f32x2 %0, %1, %2;" : "=l"(d) : "l"(a), "l"(b));
    return d;
}

// cp.async helpers (LDGSTS, 16B)
__device__ __forceinline__ unsigned int smem_u32(const void* p) {
    unsigned int a;
    asm("{ .reg .u64 t; cvta.to.shared.u64 t, %1; cvt.u32.u64 %0, t; }"
        : "=r"(a) : "l"(p));
    return a;
}
__device__ __forceinline__ void cp16(unsigned int dst, const void* src) {
    asm volatile("cp.async.cg.shared.global [%0], [%1], 16;"
                 :: "r"(dst), "l"(src) : "memory");
}
__device__ __forceinline__ void cp_commit() {
    asm volatile("cp.async.commit_group;" ::: "memory");
}
__device__ __forceinline__ void cp_wait0() {
    asm volatile("cp.async.wait_group 0;" ::: "memory");
}

// ---------------------------------------------------------------------------
// Projection GEMM v2: out = X @ W, X:[131072,384], W:[384,64].
// Tile: 256(M) x 64(N), K-chunk 32, 256 threads, thread tile 8M x 8N.
// f32x2 packing along M: A tile stored TRANSPOSED in smem (As[kk][m]) so the
// A operand loads directly as f32x2 pairs (LDS.128, no packing); only the 8
// B scalars per kk need pack2(b,b). Inner loop: 32 FFMA2 + 4 LDS.128 + ~10
// movs -> FMA-pipe-bound with issue headroom (v1 was issue-bound at ~50%).
// Register-staged double buffer, one barrier per K-chunk. 80KB dynamic smem.
// smem float layout per buffer b: As at b*10240 (32x256), Bs at +8192 (32x64).
// ---------------------------------------------------------------------------
#define ASOFF(b) ((b) * 10240)
#define BSOFF(b) ((b) * 10240 + 8192)

__global__ __launch_bounds__(256, 1)
void proj_kernel(const float* __restrict__ X,
                 const float* __restrict__ Wk,
                 const float* __restrict__ Wq,
                 const float* __restrict__ Wv) {
    extern __shared__ __align__(16) float sp[];

    const int tid = threadIdx.x;
    const int wsel = blockIdx.y;
    const float* __restrict__ W = (wsel == 0) ? Wk : (wsel == 1) ? Wq : Wv;
    float* __restrict__ dst = (wsel == 0) ? g_k : (wsel == 1) ? g_q : g_v;

    const size_t m0 = (size_t)blockIdx.x * 256;

    const int tx = tid & 7;    // 0..7  -> n0 = tx*8
    const int ty = tid >> 3;   // 0..31 -> rows mb..mb+7
    const int n0 = tx * 8;
    const int mb = ty * 8;

    // B-tile per-thread load coords: 32x64 floats = 512 float4, 2 per thread
    int bRow[2], bC4[2];
#pragma unroll
    for (int i = 0; i < 2; i++) {
        int idx = tid + i * 256;
        bRow[i] = idx >> 4;      // 16 float4 per 64-float row
        bC4[i]  = idx & 15;
    }

    float4 aReg[8], bReg[2];
    const float* xRow = X + (m0 + tid) * C_;   // A: thread owns row m0+tid

    // ---- prefetch + store chunk 0 ----
#pragma unroll
    for (int i = 0; i < 8; i++)
        aReg[i] = *(const float4*)&xRow[i * 4];
#pragma unroll
    for (int i = 0; i < 2; i++)
        bReg[i] = *(const float4*)&W[(size_t)bRow[i] * H_ + bC4[i] * 4];
#pragma unroll
    for (int i = 0; i < 8; i++) {              // transposed A store
        const int base = ASOFF(0) + (i * 4) * 256 + tid;
        sp[base]       = aReg[i].x;
        sp[base + 256] = aReg[i].y;
        sp[base + 512] = aReg[i].z;
        sp[base + 768] = aReg[i].w;
    }
#pragma unroll
    for (int i = 0; i < 2; i++)
        *(float4*)&sp[BSOFF(0) + bRow[i] * 64 + bC4[i] * 4] = bReg[i];
    __syncthreads();

    ull acc[4][8];
#pragma unroll
    for (int mp = 0; mp < 4; mp++)
#pragma unroll
        for (int n = 0; n < 8; n++) acc[mp][n] = 0ULL;

    int p = 0;
    for (int k0 = 0; k0 < C_; k0 += 32) {
        const bool more = (k0 + 32 < C_);
        // ---- issue next chunk's global loads (overlap with compute) ----
        if (more) {
            const int kn = k0 + 32;
#pragma unroll
            for (int i = 0; i < 8; i++)
                aReg[i] = *(const float4*)&xRow[kn + i * 4];
#pragma unroll
            for (int i = 0; i < 2; i++)
                bReg[i] = *(const float4*)&W[(size_t)(kn + bRow[i]) * H_ + bC4[i] * 4];
        }

        // ---- compute on buffer p: 32 kk x 32 FFMA2 ----
        const float* As = sp + ASOFF(p);
        const float* Bs = sp + BSOFF(p);
#pragma unroll 8
        for (int kk = 0; kk < 32; kk++) {
            const ulonglong2 a01 = *(const ulonglong2*)&As[kk * 256 + mb];
            const ulonglong2 a23 = *(const ulonglong2*)&As[kk * 256 + mb + 4];
            const ull am0 = a01.x, am1 = a01.y, am2 = a23.x, am3 = a23.y;
            const float4 b0 = *(const float4*)&Bs[kk * 64 + n0];
            const float4 b1 = *(const float4*)&Bs[kk * 64 + n0 + 4];
            const float bb[8] = {b0.x, b0.y, b0.z, b0.w, b1.x, b1.y, b1.z, b1.w};
#pragma unroll
            for (int n = 0; n < 8; n++) {
                const ull b2 = pack2(bb[n], bb[n]);
                acc[0][n] = fma2(am0, b2, acc[0][n]);
                acc[1][n] = fma2(am1, b2, acc[1][n]);
                acc[2][n] = fma2(am2, b2, acc[2][n]);
                acc[3][n] = fma2(am3, b2, acc[3][n]);
            }
        }

        // ---- store next chunk into other buffer, single barrier ----
        if (more) {
            const int np = p ^ 1;
#pragma unroll
            for (int i = 0; i < 8; i++) {
                const int base = ASOFF(np) + (i * 4) * 256 + tid;
                sp[base]       = aReg[i].x;
                sp[base + 256] = aReg[i].y;
                sp[base + 512] = aReg[i].z;
                sp[base + 768] = aReg[i].w;
            }
#pragma unroll
            for (int i = 0; i < 2; i++)
                *(float4*)&sp[BSOFF(np) + bRow[i] * 64 + bC4[i] * 4] = bReg[i];
            __syncthreads();
            p = np;
        }
    }

    // ---- epilogue: unpack M-pairs into row-major stores ----
#pragma unroll
    for (int mp = 0; mp < 4; mp++) {
        float r0[8], r1[8];
#pragma unroll
        for (int n = 0; n < 8; n++) unpack2(acc[mp][n], r0[n], r1[n]);
        float* o0 = dst + (m0 + mb + 2 * mp) * H_ + n0;
        float* o1 = o0 + H_;
        *(float4*)&o0[0] = make_float4(r0[0], r0[1], r0[2], r0[3]);
        *(float4*)&o0[4] = make_float4(r0[4], r0[5], r0[6], r0[7]);
        *(float4*)&o1[0] = make_float4(r1[0], r1[1], r1[2], r1[3]);
        *(float4*)&o1[4] = make_float4(r1[4], r1[5], r1[6], r1[7]);
    }
}

// ---------------------------------------------------------------------------
// Attention: one block per batch. SMSP-balanced warp->query-range map:
//   warp w (SMSP = w%4) handles queries qbase(w)..qbase(w)+31 where
//   qbase = (w<4 ? 7-w : w-4)*32; SMSP warp pairs sum to a constant 286
//   key-units of causal work. Online softmax; K/V double-buffered via
//   cp.async in 64KB dynamic smem; one barrier per chunk; masked-block skip;
//   rescale skipped when running max unchanged. (Unchanged this round to
//   isolate the proj delta.)
// ---------------------------------------------------------------------------
__global__ __launch_bounds__(256, 1)
void attn_kernel(float* __restrict__ out) {
    extern __shared__ __align__(16) float sm[];

    const int b = blockIdx.x;
    const int t = threadIdx.x;
    const int w = t >> 5;
    const int lane = t & 31;
    const int q = ((w < 4) ? (7 - w) : (w - 4)) * 32 + lane;

    const unsigned int sbase = smem_u32(sm);

    int ldRow[4], ldC4[4];
#pragma unroll
    for (int i = 0; i < 4; i++) {
        int idx = t + i * 256;
        ldRow[i] = idx >> 4;
        ldC4[i]  = idx & 15;
    }

    ull q2[32];
    {
        const ulonglong2* qp =
            (const ulonglong2*)(g_q + ((size_t)b * T_ + q) * H_);
#pragma unroll
        for (int h4 = 0; h4 < 16; h4++) {
            ulonglong2 v = qp[h4];
            q2[2 * h4]     = v.x;
            q2[2 * h4 + 1] = v.y;
        }
    }

    ull a2[32];
#pragma unroll
    for (int h2 = 0; h2 < 32; h2++) a2[h2] = 0ULL;
    float m = -INFINITY;
    float l = 0.0f;

    {
        const size_t base = (size_t)b * T_ * H_;
#pragma unroll
        for (int i = 0; i < 4; i++) {
            const unsigned int off = (unsigned)(ldRow[i] * 256 + ldC4[i] * 16);
            cp16(sbase + off,          &g_k[base + (size_t)ldRow[i] * H_ + ldC4[i] * 4]);
            cp16(sbase + 16384 + off,  &g_v[base + (size_t)ldRow[i] * H_ + ldC4[i] * 4]);
        }
        cp_commit();
    }

    int p = 0;
    for (int c = 0; c < 4; c++) {
        cp_wait0();
        __syncthreads();

        if (c < 3) {
            const size_t base = ((size_t)b * T_ + (c + 1) * 64) * H_;
            const unsigned int bb = sbase + (unsigned)((p ^ 1) * 32768);
#pragma unroll
            for (int i = 0; i < 4; i++) {
                const unsigned int off = (unsigned)(ldRow[i] * 256 + ldC4[i] * 16);
                cp16(bb + off,         &g_k[base + (size_t)ldRow[i] * H_ + ldC4[i] * 4]);
                cp16(bb + 16384 + off, &g_v[base + (size_t)ldRow[i] * H_ + ldC4[i] * 4]);
            }
            cp_commit();
        }

        const int smax = c * 64;
        if ((q | 31) >= smax) {
            const float* Ks = sm + p * 8192;
            const float* Vs = sm + p * 8192 + 4096;

            for (int j0 = 0; j0 < 64; j0 += 8) {
                if (smax + j0 > q) break;

                float sc[8];
#pragma unroll
                for (int jj = 0; jj < 8; jj++) {
                    const ulonglong2* kp =
                        (const ulonglong2*)&Ks[(j0 + jj) * 64];
                    ull d2a = 0ULL, d2b = 0ULL;
#pragma unroll
                    for (int h4 = 0; h4 < 16; h4++) {
                        ulonglong2 kv = kp[h4];
                        d2a = fma2(q2[2 * h4],     kv.x, d2a);
                        d2b = fma2(q2[2 * h4 + 1], kv.y, d2b);
                    }
                    float lo, hi;
                    unpack2(add2(d2a, d2b), lo, hi);
                    float s = (lo + hi) * 0.125f;
                    if (smax + j0 + jj > q) s = -INFINITY;
                    sc[jj] = s;
                }

                float mx = sc[0];
#pragma unroll
                for (int jj = 1; jj < 8; jj++) mx = fmaxf(mx, sc[jj]);
                const float m_new = fmaxf(m, mx);
                float wgt[8];
                float ls = 0.0f;
#pragma unroll
                for (int jj = 0; jj < 8; jj++) {
                    wgt[jj] = __expf(sc[jj] - m_new);
                    ls += wgt[jj];
                }
                if (m_new > m) {
                    const float scale = __expf(m - m_new);
                    l = l * scale + ls;
                    const ull s2 = pack2(scale, scale);
#pragma unroll
                    for (int h2 = 0; h2 < 32; h2++) a2[h2] = mul2(a2[h2], s2);
                    m = m_new;
                } else {
                    l += ls;
                }

#pragma unroll
                for (int jj = 0; jj < 8; jj++) {
                    const ull w2 = pack2(wgt[jj], wgt[jj]);
                    const ulonglong2* vp =
                        (const ulonglong2*)&Vs[(j0 + jj) * 64];
#pragma unroll
                    for (int h4 = 0; h4 < 16; h4++) {
                        ulonglong2 vv = vp[h4];
                        a2[2 * h4]     = fma2(w2, vv.x, a2[2 * h4]);
                        a2[2 * h4 + 1] = fma2(w2, vv.y, a2[2 * h4 + 1]);
                    }
                }
            }
        }
        p ^= 1;
    }

    const float inv = 1.0f / l;
    float* outr = out + ((size_t)b * T_ + q) * H_;
#pragma unroll
    for (int h2 = 0; h2 < 32; h2++) {
        float lo, hi;
        unpack2(a2[h2], lo, hi);
        *(float2*)&outr[2 * h2] = make_float2(lo * inv, hi * inv);
    }
}

// ---------------------------------------------------------------------------
// Launch: inputs per metadata order: x, Wk, Wq, Wv (all float32).
// Output: [B, T, H] float32. No static guards (harness rule);
// cudaFuncSetAttribute is host-side, non-allocating, graph-capture legal.
// ---------------------------------------------------------------------------
extern "C" void kernel_launch(void* const* d_in, const int* in_sizes, int n_in,
                              void* d_out, int out_size) {
    const float* x  = (const float*)d_in[0];
    const float* Wk = (const float*)d_in[1];
    const float* Wq = (const float*)d_in[2];
    const float* Wv = (const float*)d_in[3];
    float* out = (float*)d_out;

    cudaFuncSetAttribute(proj_kernel,
                         cudaFuncAttributeMaxDynamicSharedMemorySize,
                         80 * 1024);
    cudaFuncSetAttribute(attn_kernel,
                         cudaFuncAttributeMaxDynamicSharedMemorySize,
                         64 * 1024);

    dim3 pgrid(M_TOTAL / 256, 3);
    proj_kernel<<<pgrid, 256, 80 * 1024>>>(x, Wk, Wq, Wv);
    attn_kernel<<<B_, 256, 64 * 1024>>>(out);
}